// round 14
// baseline (speedup 1.0000x reference)
#include <cuda_runtime.h>
#include <cuda_fp16.h>
#include <cstdint>

#define NS 48
#define BDIM 32768
#define KDIM 1536
#define KT 24              // K chunks of 64
#define STAGES 3
#define BM 128
#define BN 128
#define NTHR 128
#define A_STG 16384        // 128 rows x 128B (fp16)
#define B_STG 16384        // 128 rows x 128B (fp16)
#define STAGE_BYTES (A_STG + B_STG)          // 32768
#define GEMM_SMEM (STAGES * STAGE_BYTES)     // 98304 -> 2 CTAs/SM

#define NTILES 3072        // 256 m-tiles x 12 n-tiles
#define GRIDP  296         // persistent CTAs = 148 SMs x 2

#define NB_W   192         // 6 s-groups (of 8) x 32 f
#define NB_CVT 1920        // conversion blocks
#define NB_PRE (NB_W + NB_CVT)

// ---------------- device-global scratch (no runtime allocation allowed) ----
__device__ __half g_x16[(size_t)BDIM * KDIM];   // x in fp16
__device__ __half g_W[(size_t)KDIM * KDIM];     // fused operator [N=1536][K=1536], K contiguous
__device__ float  g_biasx[KDIM];                // bias broadcast over t

// ---------------- PTX helpers ---------------------------------------------
__device__ __forceinline__ unsigned s2u(const void* p) {
    return (unsigned)__cvta_generic_to_shared(p);
}
__device__ __forceinline__ void cpa16(unsigned s, const void* g) {
    asm volatile("cp.async.cg.shared.global [%0], [%1], 16;" :: "r"(s), "l"(g));
}
#define CPA_COMMIT asm volatile("cp.async.commit_group;" ::: "memory")
#define CPA_WAIT1  asm volatile("cp.async.wait_group 1;" ::: "memory")

__device__ __forceinline__ void ldsm4(unsigned* r, unsigned addr) {
    asm volatile("ldmatrix.sync.aligned.m8n8.x4.shared.b16 {%0,%1,%2,%3}, [%4];"
                 : "=r"(r[0]), "=r"(r[1]), "=r"(r[2]), "=r"(r[3]) : "r"(addr));
}
__device__ __forceinline__ void mma16816(float* d, const unsigned* a,
                                         unsigned b0, unsigned b1) {
    asm volatile(
        "mma.sync.aligned.m16n8k16.row.col.f32.f16.f16.f32 "
        "{%0,%1,%2,%3}, {%4,%5,%6,%7}, {%8,%9}, {%0,%1,%2,%3};"
        : "+f"(d[0]), "+f"(d[1]), "+f"(d[2]), "+f"(d[3])
        : "r"(a[0]), "r"(a[1]), "r"(a[2]), "r"(a[3]), "r"(b0), "r"(b1));
}

// ---------------- ONE fused pre-pass kernel ---------------------------------
// 1-D grid, 256 threads.
//  block <  NB_W : W-tile. s-group = b%6 (8 s-values), f = b/6. fwd + kh
//                  built ONCE, reused across 8 s (U per s is cheap).
//  block >= NB_W : grid-strided fp32->fp16 conversion of x. Block NB_W also
//                  fills the bias broadcast.

__device__ __forceinline__ void decode_o(int o, int& d, int& base, int& a, int& b) {
    if (o < 4)       { d = 1; base = o; a = 0; b = 0; }
    else if (o < 12) { int rem = o - 4;  d = 2; base = 4 + (rem >> 2) * 4; rem &= 3;  a = rem >> 1; b = rem & 1; }
    else             { int rem = o - 12; d = 3; base = 12 + (rem / 9) * 9; rem %= 9; a = rem / 3;  b = rem % 3; }
}

__global__ void __launch_bounds__(256) k_pre(
        const float4* __restrict__ x, const float* __restrict__ kern,
        const float* __restrict__ bias,
        const float* __restrict__ d1, const float* __restrict__ d2,
        const float* __restrict__ d3) {
    int blk = blockIdx.x;
    if (blk >= NB_W) {                  // ---- conversion / bias planes ----
        if (blk == NB_W)
            for (int j = threadIdx.x; j < KDIM; j += 256)
                g_biasx[j] = bias[j / NS];
        size_t n4 = (size_t)BDIM * KDIM / 4;
        size_t cid = (size_t)(blk - NB_W);
        __half2* o = (__half2*)g_x16;
        for (size_t i = cid * 256 + threadIdx.x; i < n4;
             i += (size_t)NB_CVT * 256) {
            float4 v = x[i];
            o[2 * i]     = __floats2half2_rn(v.x, v.y);
            o[2 * i + 1] = __floats2half2_rn(v.z, v.w);
        }
        return;
    }

    // ---- W tile: 8 s-values, one f ----
    int sgrp = blk % 6, f = blk / 6;
    __shared__ float sf[NS * NS];        // fwd [s'][o]
    __shared__ float kt_[32 * NS];       // kern rows [c][s']
    __shared__ float Us[NS * NS];        // U[s] as [t][o2] (rebuilt per s)
    __shared__ float khs[32 * (NS + 1)]; // kh slice [c][o2], padded

    for (int idx = threadIdx.x; idx < NS * NS; idx += 256) {
        int sp = idx / NS, o = idx % NS;
        float v;
        if (o < 4)       v = d1[o * NS + sp];
        else if (o < 12) { int rem = o - 4;  v = d2[((rem >> 2) * NS + sp) * 4 + (rem & 3)]; }
        else             { int rem = o - 12; v = d3[((rem / 9) * NS + sp) * 9 + (rem % 9)]; }
        sf[sp * NS + o] = v;
    }
    for (int idx = threadIdx.x; idx < 32 * NS; idx += 256)
        kt_[idx] = kern[(size_t)(f * 32) * NS + idx];
    __syncthreads();

    // kh[c][o] = sum_s' kern[f*32+c, s'] * fwd[s', o]   (once per CTA)
    for (int e = threadIdx.x; e < 32 * NS; e += 256) {
        int c = e / NS, o = e % NS;
        float acc = 0.f;
#pragma unroll
        for (int sp = 0; sp < NS; sp++) acc += kt_[c * NS + sp] * sf[sp * NS + o];
        khs[c * (NS + 1) + o] = acc;
    }
    __syncthreads();

    int c = threadIdx.x & 31, t0 = threadIdx.x >> 5;
    float kr[NS];
#pragma unroll
    for (int o2 = 0; o2 < NS; o2++) kr[o2] = khs[c * (NS + 1) + o2];

    for (int sl = 0; sl < 8; sl++) {
        int s = sgrp * 8 + sl;
        __syncthreads();                 // WAR: previous Us reads complete
        // U[s][t][o2] = (d/48) sum_p fwd[s,(n,p,r)] fwd[t,(n,p,q)]
        for (int e = threadIdx.x; e < NS * NS; e += 256) {
            int t = e / NS, o2 = e % NS;
            int d, base, r, q;
            decode_o(o2, d, base, r, q);
            float acc = 0.f;
            for (int p = 0; p < d; p++)
                acc += sf[s * NS + base + p * d + r] * sf[t * NS + base + p * d + q];
            Us[t * NS + o2] = acc * (float)d * (1.0f / 48.0f);
        }
        __syncthreads();
        for (int t = t0; t < NS; t += 8) {
            const float4* u = (const float4*)(Us + t * NS);
            float acc = 0.f;
#pragma unroll
            for (int i = 0; i < 12; i++) {
                float4 v = u[i];
                acc += kr[4 * i] * v.x + kr[4 * i + 1] * v.y
                     + kr[4 * i + 2] * v.z + kr[4 * i + 3] * v.w;
            }
            g_W[(size_t)(f * NS + t) * KDIM + c * NS + s] = __float2half_rn(acc);
        }
    }
}

// ---------------- main GEMM: persistent CTAs --------------------------------
// 128x128 tile, 128 threads = 4 warps (2x2), warp tile 64x64 (acc 128).
// 3 stages x 32KB -> 2 CTAs/SM. Each CTA loops over tiles cta, cta+296, ...
// Per kt (proven): wait_group 1 -> __syncthreads -> issue(kt+2) -> commit ->
// mma(kt). At tile end: __syncthreads (all stage reads done) -> prefetch next
// tile's stages 0,1 -> epilogue stores overlap the prefetch.

__device__ __forceinline__ void issue_AB(int kt, int tid, unsigned sb,
                                         const __half* gx, const __half* gw) {
    unsigned sa = sb + (unsigned)(kt % STAGES) * STAGE_BYTES;
    const __half* ga = gx + kt * 64;
    const __half* gb = gw + kt * 64;
#pragma unroll
    for (int it = 0; it < 8; it++) {            // A: 1024 16B chunks
        int j = tid + it * NTHR;
        int r = j >> 3, c = j & 7;
        unsigned soff = (unsigned)r * 128u + (unsigned)((c ^ (r & 7)) << 4);
        cpa16(sa + soff, ga + (size_t)r * KDIM + c * 8);
    }
#pragma unroll
    for (int it = 0; it < 8; it++) {            // B: 1024 16B chunks
        int j = tid + it * NTHR;
        int r = j >> 3, c = j & 7;
        unsigned soff = (unsigned)A_STG + (unsigned)r * 128u
                      + (unsigned)((c ^ (r & 7)) << 4);
        cpa16(sa + soff, gb + (size_t)r * KDIM + c * 8);
    }
}

__global__ void __launch_bounds__(NTHR, 2) k_gemm(float* __restrict__ out) {
    extern __shared__ char smem[];
    unsigned sb = s2u(smem);
    int tid = threadIdx.x, lane = tid & 31, wid = tid >> 5;
    int wm = wid & 1, wn = wid >> 1;             // 2x2 warp grid

    unsigned rowA = lane & 15;
    unsigned hkA  = lane >> 4;
    unsigned rowB = (lane & 7) | ((lane & 16) >> 1);
    unsigned ckB  = (lane >> 3) & 1;
    unsigned xorA = (lane & 7) << 4;

    float acc[4][8][4];
#pragma unroll
    for (int i = 0; i < 4; i++)
#pragma unroll
        for (int j = 0; j < 8; j++)
#pragma unroll
            for (int e = 0; e < 4; e++) acc[i][j][e] = 0.f;

    int t = blockIdx.x;
    int n0 = (t % 12) * BN, m0 = (t / 12) * BM;
    const __half* gx = g_x16 + (size_t)m0 * KDIM;
    const __half* gw = g_W   + (size_t)n0 * KDIM;

    // first-tile prologue
    issue_AB(0, tid, sb, gx, gw); CPA_COMMIT;
    issue_AB(1, tid, sb, gx, gw); CPA_COMMIT;

    for (; t < NTILES; t += GRIDP) {
        // ---- mainloop over K ----
        for (int kt = 0; kt < KT; kt++) {
            CPA_WAIT1;                    // group kt complete (my chunks)
            __syncthreads();              // everyone's chunks visible; kt-1 reads done
            if (kt + 2 < KT) issue_AB(kt + 2, tid, sb, gx, gw);
            CPA_COMMIT;
            unsigned stg   = sb + (unsigned)(kt % STAGES) * STAGE_BYTES;
            unsigned baseA = stg + (unsigned)wm * (64 * 128) + rowA * 128;
            unsigned baseB = stg + A_STG + (unsigned)wn * (64 * 128) + rowB * 128;
#pragma unroll
            for (int s4 = 0; s4 < 4; s4++) {
                unsigned a[4][4], b[4][4];
                unsigned chA = (((2 * s4 + hkA) << 4) ^ xorA);
                unsigned chB = (((2 * s4 + ckB) << 4) ^ xorA);
#pragma unroll
                for (int mi = 0; mi < 4; mi++) ldsm4(a[mi], baseA + mi * 2048 + chA);
#pragma unroll
                for (int nj = 0; nj < 4; nj++) ldsm4(b[nj], baseB + nj * 2048 + chB);
#pragma unroll
                for (int mi = 0; mi < 4; mi++)
#pragma unroll
                    for (int nj = 0; nj < 8; nj++)
                        mma16816(acc[mi][nj], a[mi],
                                 b[nj >> 1][(nj & 1) * 2], b[nj >> 1][(nj & 1) * 2 + 1]);
            }
        }

        // ---- tile transition: prefetch next tile, then epilogue ----
        __syncthreads();                  // all warps done reading all stages
        int tn = t + GRIDP;
        if (tn < NTILES) {
            const __half* gx2 = g_x16 + (size_t)((tn / 12) * BM) * KDIM;
            const __half* gw2 = g_W   + (size_t)((tn % 12) * BN) * KDIM;
            issue_AB(0, tid, sb, gx2, gw2); CPA_COMMIT;
            issue_AB(1, tid, sb, gx2, gw2); CPA_COMMIT;
            gx = gx2; gw = gw2;
        }

        // epilogue for current tile (overlaps the prefetch above)
        int rbase = m0 + wm * 64 + (lane >> 2);
        int cbase = n0 + wn * 64 + 2 * (lane & 3);
#pragma unroll
        for (int nj = 0; nj < 8; nj++) {
            int col = cbase + nj * 8;
            float b0 = g_biasx[col], b1 = g_biasx[col + 1];
#pragma unroll
            for (int mi = 0; mi < 4; mi++) {
                int r0 = rbase + mi * 16;
                float2 v0 = make_float2(acc[mi][nj][0] + b0, acc[mi][nj][1] + b1);
                float2 v1 = make_float2(acc[mi][nj][2] + b0, acc[mi][nj][3] + b1);
                *(float2*)&out[(size_t)r0 * KDIM + col] = v0;
                *(float2*)&out[(size_t)(r0 + 8) * KDIM + col] = v1;
            }
        }
#pragma unroll
        for (int i = 0; i < 4; i++)
#pragma unroll
            for (int j = 0; j < 8; j++)
#pragma unroll
                for (int e = 0; e < 4; e++) acc[i][j][e] = 0.f;
        n0 = ((t + GRIDP) % 12) * BN;
        m0 = ((t + GRIDP) / 12) * BM;
    }
}

// ---------------- launch ----------------------------------------------------
extern "C" void kernel_launch(void* const* d_in, const int* in_sizes, int n_in,
                              void* d_out, int out_size) {
    const float* x    = (const float*)d_in[0];
    const float* kern = (const float*)d_in[1];
    const float* bias = (const float*)d_in[2];
    const float* d1   = (const float*)d_in[3];
    const float* d2   = (const float*)d_in[4];
    const float* d3   = (const float*)d_in[5];
    float* out = (float*)d_out;

    k_pre<<<NB_PRE, 256>>>((const float4*)x, kern, bias, d1, d2, d3);

    cudaFuncSetAttribute(k_gemm, cudaFuncAttributeMaxDynamicSharedMemorySize, GEMM_SMEM);
    k_gemm<<<GRIDP, NTHR, GEMM_SMEM>>>(out);
}

// round 15
// speedup vs baseline: 1.0671x; 1.0671x over previous
#include <cuda_runtime.h>
#include <cuda_fp16.h>
#include <cstdint>

#define NS 48
#define BDIM 32768
#define KDIM 1536
#define KT 24              // K chunks of 64
#define STAGES 3
#define BM 128
#define BN 128
#define NTHR 128
#define A_STG 16384        // 128 rows x 128B (fp16)
#define B_STG 16384        // 128 rows x 128B (fp16)
#define STAGE_BYTES (A_STG + B_STG)          // 32768
#define GEMM_SMEM (STAGES * STAGE_BYTES)     // 98304 -> 2 CTAs/SM

#define NB_W   192         // 6 s-groups (of 8) x 32 f
#define NB_CVT 1920        // conversion blocks
#define NB_PRE (NB_W + NB_CVT)

// ---------------- device-global scratch (no runtime allocation allowed) ----
__device__ __half g_x16[(size_t)BDIM * KDIM];   // x in fp16
__device__ __half g_W[(size_t)KDIM * KDIM];     // fused operator [N=1536][K=1536], K contiguous
__device__ float  g_biasx[KDIM];                // bias broadcast over t

// ---------------- PTX helpers ---------------------------------------------
__device__ __forceinline__ unsigned s2u(const void* p) {
    return (unsigned)__cvta_generic_to_shared(p);
}
__device__ __forceinline__ void cpa16(unsigned s, const void* g) {
    asm volatile("cp.async.cg.shared.global [%0], [%1], 16;" :: "r"(s), "l"(g));
}
#define CPA_COMMIT asm volatile("cp.async.commit_group;" ::: "memory")
#define CPA_WAIT1  asm volatile("cp.async.wait_group 1;" ::: "memory")

__device__ __forceinline__ void ldsm4(unsigned* r, unsigned addr) {
    asm volatile("ldmatrix.sync.aligned.m8n8.x4.shared.b16 {%0,%1,%2,%3}, [%4];"
                 : "=r"(r[0]), "=r"(r[1]), "=r"(r[2]), "=r"(r[3]) : "r"(addr));
}
__device__ __forceinline__ void mma16816(float* d, const unsigned* a,
                                         unsigned b0, unsigned b1) {
    asm volatile(
        "mma.sync.aligned.m16n8k16.row.col.f32.f16.f16.f32 "
        "{%0,%1,%2,%3}, {%4,%5,%6,%7}, {%8,%9}, {%0,%1,%2,%3};"
        : "+f"(d[0]), "+f"(d[1]), "+f"(d[2]), "+f"(d[3])
        : "r"(a[0]), "r"(a[1]), "r"(a[2]), "r"(a[3]), "r"(b0), "r"(b1));
}

// ---------------- ONE fused pre-pass kernel (R14-proven, ~52us) -------------
// 1-D grid, 256 threads.
//  block <  NB_W : W-tile. s-group = b%6 (8 s-values), f = b/6. fwd + kh
//                  built ONCE, reused across 8 s (U per s is cheap).
//  block >= NB_W : grid-strided fp32->fp16 conversion of x. Block NB_W also
//                  fills the bias broadcast.

__device__ __forceinline__ void decode_o(int o, int& d, int& base, int& a, int& b) {
    if (o < 4)       { d = 1; base = o; a = 0; b = 0; }
    else if (o < 12) { int rem = o - 4;  d = 2; base = 4 + (rem >> 2) * 4; rem &= 3;  a = rem >> 1; b = rem & 1; }
    else             { int rem = o - 12; d = 3; base = 12 + (rem / 9) * 9; rem %= 9; a = rem / 3;  b = rem % 3; }
}

__global__ void __launch_bounds__(256) k_pre(
        const float4* __restrict__ x, const float* __restrict__ kern,
        const float* __restrict__ bias,
        const float* __restrict__ d1, const float* __restrict__ d2,
        const float* __restrict__ d3) {
    int blk = blockIdx.x;
    if (blk >= NB_W) {                  // ---- conversion / bias planes ----
        if (blk == NB_W)
            for (int j = threadIdx.x; j < KDIM; j += 256)
                g_biasx[j] = bias[j / NS];
        size_t n4 = (size_t)BDIM * KDIM / 4;
        size_t cid = (size_t)(blk - NB_W);
        __half2* o = (__half2*)g_x16;
        for (size_t i = cid * 256 + threadIdx.x; i < n4;
             i += (size_t)NB_CVT * 256) {
            float4 v = x[i];
            o[2 * i]     = __floats2half2_rn(v.x, v.y);
            o[2 * i + 1] = __floats2half2_rn(v.z, v.w);
        }
        return;
    }

    // ---- W tile: 8 s-values, one f ----
    int sgrp = blk % 6, f = blk / 6;
    __shared__ float sf[NS * NS];        // fwd [s'][o]
    __shared__ float kt_[32 * NS];       // kern rows [c][s']
    __shared__ float Us[NS * NS];        // U[s] as [t][o2] (rebuilt per s)
    __shared__ float khs[32 * (NS + 1)]; // kh slice [c][o2], padded

    for (int idx = threadIdx.x; idx < NS * NS; idx += 256) {
        int sp = idx / NS, o = idx % NS;
        float v;
        if (o < 4)       v = d1[o * NS + sp];
        else if (o < 12) { int rem = o - 4;  v = d2[((rem >> 2) * NS + sp) * 4 + (rem & 3)]; }
        else             { int rem = o - 12; v = d3[((rem / 9) * NS + sp) * 9 + (rem % 9)]; }
        sf[sp * NS + o] = v;
    }
    for (int idx = threadIdx.x; idx < 32 * NS; idx += 256)
        kt_[idx] = kern[(size_t)(f * 32) * NS + idx];
    __syncthreads();

    // kh[c][o] = sum_s' kern[f*32+c, s'] * fwd[s', o]   (once per CTA)
    for (int e = threadIdx.x; e < 32 * NS; e += 256) {
        int c = e / NS, o = e % NS;
        float acc = 0.f;
#pragma unroll
        for (int sp = 0; sp < NS; sp++) acc += kt_[c * NS + sp] * sf[sp * NS + o];
        khs[c * (NS + 1) + o] = acc;
    }
    __syncthreads();

    int c = threadIdx.x & 31, t0 = threadIdx.x >> 5;
    float kr[NS];
#pragma unroll
    for (int o2 = 0; o2 < NS; o2++) kr[o2] = khs[c * (NS + 1) + o2];

    for (int sl = 0; sl < 8; sl++) {
        int s = sgrp * 8 + sl;
        __syncthreads();                 // WAR: previous Us reads complete
        // U[s][t][o2] = (d/48) sum_p fwd[s,(n,p,r)] fwd[t,(n,p,q)]
        for (int e = threadIdx.x; e < NS * NS; e += 256) {
            int t = e / NS, o2 = e % NS;
            int d, base, r, q;
            decode_o(o2, d, base, r, q);
            float acc = 0.f;
            for (int p = 0; p < d; p++)
                acc += sf[s * NS + base + p * d + r] * sf[t * NS + base + p * d + q];
            Us[t * NS + o2] = acc * (float)d * (1.0f / 48.0f);
        }
        __syncthreads();
        for (int t = t0; t < NS; t += 8) {
            const float4* u = (const float4*)(Us + t * NS);
            float acc = 0.f;
#pragma unroll
            for (int i = 0; i < 12; i++) {
                float4 v = u[i];
                acc += kr[4 * i] * v.x + kr[4 * i + 1] * v.y
                     + kr[4 * i + 2] * v.z + kr[4 * i + 3] * v.w;
            }
            g_W[(size_t)(f * NS + t) * KDIM + c * NS + s] = __float2half_rn(acc);
        }
    }
}

// ---------------- main GEMM (R13-proven: 348.6us, tensor 73.3%) -------------
// 128x128 CTA tile, 128 threads = 4 warps (2x2), warp tile 64x64 (acc 128).
// 3 stages x 32KB -> 2 CTAs/SM; both A (g_x16) and B (g_W) via cp.async.
// Schedule per kt: wait_group 1 -> __syncthreads -> issue(kt+2) -> commit ->
// mma(kt).

__device__ __forceinline__ void issue_AB(int kt, int tid, unsigned sb,
                                         const __half* gx, const __half* gw) {
    unsigned sa = sb + (unsigned)(kt % STAGES) * STAGE_BYTES;
    const __half* ga = gx + kt * 64;
    const __half* gb = gw + kt * 64;
#pragma unroll
    for (int it = 0; it < 8; it++) {            // A: 1024 16B chunks
        int j = tid + it * NTHR;
        int r = j >> 3, c = j & 7;
        unsigned soff = (unsigned)r * 128u + (unsigned)((c ^ (r & 7)) << 4);
        cpa16(sa + soff, ga + (size_t)r * KDIM + c * 8);
    }
#pragma unroll
    for (int it = 0; it < 8; it++) {            // B: 1024 16B chunks
        int j = tid + it * NTHR;
        int r = j >> 3, c = j & 7;
        unsigned soff = (unsigned)A_STG + (unsigned)r * 128u
                      + (unsigned)((c ^ (r & 7)) << 4);
        cpa16(sa + soff, gb + (size_t)r * KDIM + c * 8);
    }
}

__global__ void __launch_bounds__(NTHR, 2) k_gemm(float* __restrict__ out) {
    extern __shared__ char smem[];
    unsigned sb = s2u(smem);
    int tid = threadIdx.x, lane = tid & 31, wid = tid >> 5;
    int wm = wid & 1, wn = wid >> 1;             // 2x2 warp grid
    int n0 = blockIdx.x * BN, m0 = blockIdx.y * BM;

    const __half* gx = g_x16 + (size_t)m0 * KDIM;
    const __half* gw = g_W   + (size_t)n0 * KDIM;

    float acc[4][8][4];
#pragma unroll
    for (int i = 0; i < 4; i++)
#pragma unroll
        for (int j = 0; j < 8; j++)
#pragma unroll
            for (int e = 0; e < 4; e++) acc[i][j][e] = 0.f;

    unsigned rowA = lane & 15;
    unsigned hkA  = lane >> 4;
    unsigned rowB = (lane & 7) | ((lane & 16) >> 1);
    unsigned ckB  = (lane >> 3) & 1;
    unsigned xorA = (lane & 7) << 4;

    // prologue: stages 0,1
    issue_AB(0, tid, sb, gx, gw); CPA_COMMIT;
    issue_AB(1, tid, sb, gx, gw); CPA_COMMIT;

    for (int kt = 0; kt < KT; kt++) {
        CPA_WAIT1;                    // group kt complete (my chunks)
        __syncthreads();              // everyone's chunks visible; kt-1 reads done
        if (kt + 2 < KT) issue_AB(kt + 2, tid, sb, gx, gw);
        CPA_COMMIT;
        unsigned stg   = sb + (unsigned)(kt % STAGES) * STAGE_BYTES;
        unsigned baseA = stg + (unsigned)wm * (64 * 128) + rowA * 128;
        unsigned baseB = stg + A_STG + (unsigned)wn * (64 * 128) + rowB * 128;
#pragma unroll
        for (int s4 = 0; s4 < 4; s4++) {
            unsigned a[4][4], b[4][4];
            unsigned chA = (((2 * s4 + hkA) << 4) ^ xorA);
            unsigned chB = (((2 * s4 + ckB) << 4) ^ xorA);
#pragma unroll
            for (int mi = 0; mi < 4; mi++) ldsm4(a[mi], baseA + mi * 2048 + chA);
#pragma unroll
            for (int nj = 0; nj < 4; nj++) ldsm4(b[nj], baseB + nj * 2048 + chB);
#pragma unroll
            for (int mi = 0; mi < 4; mi++)
#pragma unroll
                for (int nj = 0; nj < 8; nj++)
                    mma16816(acc[mi][nj], a[mi],
                             b[nj >> 1][(nj & 1) * 2], b[nj >> 1][(nj & 1) * 2 + 1]);
        }
    }

    // ---- epilogue: direct float2 stores + bias ----
    int rbase = m0 + wm * 64 + (lane >> 2);
    int cbase = n0 + wn * 64 + 2 * (lane & 3);
#pragma unroll
    for (int nj = 0; nj < 8; nj++) {
        int col = cbase + nj * 8;
        float b0 = g_biasx[col], b1 = g_biasx[col + 1];
#pragma unroll
        for (int mi = 0; mi < 4; mi++) {
            int r0 = rbase + mi * 16;
            float2 v0 = make_float2(acc[mi][nj][0] + b0, acc[mi][nj][1] + b1);
            float2 v1 = make_float2(acc[mi][nj][2] + b0, acc[mi][nj][3] + b1);
            *(float2*)&out[(size_t)r0 * KDIM + col] = v0;
            *(float2*)&out[(size_t)(r0 + 8) * KDIM + col] = v1;
        }
    }
}

// ---------------- launch ----------------------------------------------------
extern "C" void kernel_launch(void* const* d_in, const int* in_sizes, int n_in,
                              void* d_out, int out_size) {
    const float* x    = (const float*)d_in[0];
    const float* kern = (const float*)d_in[1];
    const float* bias = (const float*)d_in[2];
    const float* d1   = (const float*)d_in[3];
    const float* d2   = (const float*)d_in[4];
    const float* d3   = (const float*)d_in[5];
    float* out = (float*)d_out;

    k_pre<<<NB_PRE, 256>>>((const float4*)x, kern, bias, d1, d2, d3);

    cudaFuncSetAttribute(k_gemm, cudaFuncAttributeMaxDynamicSharedMemorySize, GEMM_SMEM);
    k_gemm<<<dim3(KDIM / BN, BDIM / BM), NTHR, GEMM_SMEM>>>(out);
}